// round 13
// baseline (speedup 1.0000x reference)
#include <cuda_runtime.h>
#include <cuda_bf16.h>
#include <math.h>
#include <stdint.h>

#define B_ 1024
#define T_ 256
#define F_ 128
#define H_ 128
#define G4H 512
#define D_ 256
#define A_ 8
typedef unsigned long long u64;

__device__ float g_xg[(size_t)B_*T_*G4H];
__device__ float g_x[B_*H_];
__device__ float g_a1[B_*D_]; __device__ float g_v1[B_*D_];
__device__ float g_a2[B_*D_]; __device__ float g_v2[B_*D_];

// ---------------- helpers ----------------
__device__ __forceinline__ uint32_t s2u(const void* p){
  uint32_t a; asm("{ .reg .u64 t; cvta.to.shared.u64 t, %1; cvt.u32.u64 %0, t; }":"=r"(a):"l"(p)); return a;
}
__device__ __forceinline__ u64 fma2(u64 a, u64 b, u64 c){
  u64 d; asm("fma.rn.f32x2 %0,%1,%2,%3;":"=l"(d):"l"(a),"l"(b),"l"(c)); return d;
}
__device__ __forceinline__ u64 pack2(float x, float y){
  u64 r; asm("mov.b64 %0,{%1,%2};":"=l"(r):"f"(x),"f"(y)); return r;
}
__device__ __forceinline__ float2 up2(u64 v){ float2 f; asm("mov.b64 {%0,%1},%2;":"=f"(f.x),"=f"(f.y):"l"(v)); return f; }
__device__ __forceinline__ void ldsm4(uint32_t* r, uint32_t a){
  asm volatile("ldmatrix.sync.aligned.m8n8.x4.shared.b16 {%0,%1,%2,%3},[%4];"
    :"=r"(r[0]),"=r"(r[1]),"=r"(r[2]),"=r"(r[3]):"r"(a));
}
__device__ __forceinline__ void ldsm2t(uint32_t* r, uint32_t a){
  asm volatile("ldmatrix.sync.aligned.m8n8.x2.trans.shared.b16 {%0,%1},[%2];"
    :"=r"(r[0]),"=r"(r[1]):"r"(a));
}
__device__ __forceinline__ void mma16816(float* d, const uint32_t* a, const uint32_t* b){
  asm volatile("mma.sync.aligned.m16n8k16.row.col.f32.bf16.bf16.f32 "
    "{%0,%1,%2,%3},{%4,%5,%6,%7},{%8,%9},{%0,%1,%2,%3};"
    :"+f"(d[0]),"+f"(d[1]),"+f"(d[2]),"+f"(d[3])
    :"r"(a[0]),"r"(a[1]),"r"(a[2]),"r"(a[3]),"r"(b[0]),"r"(b[1]));
}
__device__ __forceinline__ float b2f(__nv_bfloat16 x){ return __bfloat162float(x); }
__device__ __forceinline__ void splitst(float4 v, __nv_bfloat16* Hs, __nv_bfloat16* Ls){
  __nv_bfloat16 h0=__float2bfloat16_rn(v.x);
  __nv_bfloat16 h1=__float2bfloat16_rn(v.y);
  __nv_bfloat16 h2=__float2bfloat16_rn(v.z);
  __nv_bfloat16 h3=__float2bfloat16_rn(v.w);
  __nv_bfloat16 l0=__float2bfloat16_rn(v.x-b2f(h0));
  __nv_bfloat16 l1=__float2bfloat16_rn(v.y-b2f(h1));
  __nv_bfloat16 l2=__float2bfloat16_rn(v.z-b2f(h2));
  __nv_bfloat16 l3=__float2bfloat16_rn(v.w-b2f(h3));
  *(__nv_bfloat162*)(Hs)  =__halves2bfloat162(h0,h1);
  *(__nv_bfloat162*)(Hs+2)=__halves2bfloat162(h2,h3);
  *(__nv_bfloat162*)(Ls)  =__halves2bfloat162(l0,l1);
  *(__nv_bfloat162*)(Ls+2)=__halves2bfloat162(l2,l3);
}

// ---------------- K1: xg = h @ Wx, bf16 hi/lo split mma --------------------
#define SA 136
__global__ void __launch_bounds__(256,1) k_xg_mma(const float* __restrict__ hin,
                                                  const float* __restrict__ Wx){
  extern __shared__ __align__(16) char smraw[];
  __nv_bfloat16 *Ah=(__nv_bfloat16*)smraw, *Al=Ah+128*SA, *Bh=Al+128*SA, *Bl=Bh+128*SA;
  const int tid=threadIdx.x, lane=tid&31, wid=tid>>5;
  const int m0=blockIdx.x*128, n0=blockIdx.y*128;

  #pragma unroll
  for(int i=0;i<16;i++){
    int idx=i*256+tid, row=idx>>5, c4=(idx&31)<<2;
    float4 a=*(const float4*)&hin[(size_t)(m0+row)*F_+c4];
    float4 b=*(const float4*)&Wx[(size_t)row*G4H+n0+c4];
    splitst(a, Ah+row*SA+c4, Al+row*SA+c4);
    splitst(b, Bh+row*SA+c4, Bl+row*SA+c4);
  }
  __syncthreads();

  const int wm=(wid>>2)*64, wn=(wid&3)*32;
  float acc[16][4];
  #pragma unroll
  for(int i=0;i<16;i++){acc[i][0]=0.f;acc[i][1]=0.f;acc[i][2]=0.f;acc[i][3]=0.f;}

  #pragma unroll
  for(int ks=0;ks<8;ks++){
    int k0=ks*16;
    uint32_t ah[4][4], al[4][4], bh[4][2], bl[4][2];
    int ar=lane&15, ac=k0+((lane>>4)<<3);
    #pragma unroll
    for(int mi=0;mi<4;mi++){
      ldsm4(ah[mi], s2u(Ah+(wm+mi*16+ar)*SA+ac));
      ldsm4(al[mi], s2u(Al+(wm+mi*16+ar)*SA+ac));
    }
    int br=k0+(lane&15);
    #pragma unroll
    for(int ni=0;ni<4;ni++){
      ldsm2t(bh[ni], s2u(Bh+br*SA+wn+ni*8));
      ldsm2t(bl[ni], s2u(Bl+br*SA+wn+ni*8));
    }
    #pragma unroll
    for(int mi=0;mi<4;mi++)
      #pragma unroll
      for(int ni=0;ni<4;ni++){
        float* d=acc[mi*4+ni];
        mma16816(d, ah[mi], bh[ni]);
        mma16816(d, ah[mi], bl[ni]);
        mma16816(d, al[mi], bh[ni]);
      }
  }
  int r=lane>>2, c2=(lane&3)*2;
  #pragma unroll
  for(int mi=0;mi<4;mi++)
    #pragma unroll
    for(int ni=0;ni<4;ni++){
      float* d=acc[mi*4+ni];
      size_t base=(size_t)(m0+wm+mi*16+r)*G4H + n0+wn+ni*8+c2;
      *(float2*)&g_xg[base]        =make_float2(d[0],d[1]);
      *(float2*)&g_xg[base+8*G4H]  =make_float2(d[2],d[3]);
    }
}

// ---------------- K2: fused LSTM, 256 thr, 2 cols/thr, f32x2 ----------------
#define KPS 48                   // k-pairs staged in smem (k < 96)
#define SWH 10                   // hsq row stride (u64)
__global__ void __launch_bounds__(256,1) k_lstm(const float* __restrict__ Wh,
                                                const float* __restrict__ bh){
  extern __shared__ __align__(16) char smraw[];
  u64*   whs=(u64*)smraw;                                  // [KPS][512]
  float* z  =(float*)(smraw + KPS*512*8);                  // [8][512]
  u64*   hsq=(u64*)((char*)z + 8*512*4);                   // [64][SWH] (8 used)
  float* cs =(float*)((char*)hsq + 64*SWH*8);              // [8][128]
  const int tid=threadIdx.x;
  const int r0 =blockIdx.x*8;
  const int c0 =tid, c1=tid+256;

  // stage whs[kp][c] — coalesced
  for(int kp=0;kp<KPS;kp++){
    whs[kp*512+c0]=pack2(Wh[(size_t)(2*kp)*G4H+c0], Wh[(size_t)(2*kp+1)*G4H+c0]);
    whs[kp*512+c1]=pack2(Wh[(size_t)(2*kp)*G4H+c1], Wh[(size_t)(2*kp+1)*G4H+c1]);
  }
  // tail weights (kp 48..63) live in registers for all 256 steps, both columns
  u64 wt0[16], wt1[16];
  #pragma unroll
  for(int i=0;i<16;i++){
    int kp=KPS+i;
    wt0[i]=pack2(Wh[(size_t)(2*kp)*G4H+c0], Wh[(size_t)(2*kp+1)*G4H+c0]);
    wt1[i]=pack2(Wh[(size_t)(2*kp)*G4H+c1], Wh[(size_t)(2*kp+1)*G4H+c1]);
  }
  for(int i=tid;i<64*SWH;i+=256) hsq[i]=0ull;
  for(int i=tid;i<1024;i+=256) cs[i]=0.f;
  const float b0=bh[c0], b1=bh[c1];
  __syncthreads();

  for(int t=0;t<T_;t++){
    float xv0[8], xv1[8];
    #pragma unroll
    for(int r=0;r<8;r++){
      size_t o=((size_t)(r0+r)*T_+t)*G4H;
      xv0[r]=g_xg[o+c0]; xv1[r]=g_xg[o+c1];
    }
    u64 a0[8], a1[8];
    #pragma unroll
    for(int r=0;r<8;r++){a0[r]=0ull;a1[r]=0ull;}

    #pragma unroll 2
    for(int kp=0;kp<KPS;kp++){
      u64 w0=whs[kp*512+c0];
      u64 w1=whs[kp*512+c1];
      ulonglong2 h01=*(const ulonglong2*)&hsq[kp*SWH+0];
      ulonglong2 h23=*(const ulonglong2*)&hsq[kp*SWH+2];
      ulonglong2 h45=*(const ulonglong2*)&hsq[kp*SWH+4];
      ulonglong2 h67=*(const ulonglong2*)&hsq[kp*SWH+6];
      a0[0]=fma2(h01.x,w0,a0[0]); a1[0]=fma2(h01.x,w1,a1[0]);
      a0[1]=fma2(h01.y,w0,a0[1]); a1[1]=fma2(h01.y,w1,a1[1]);
      a0[2]=fma2(h23.x,w0,a0[2]); a1[2]=fma2(h23.x,w1,a1[2]);
      a0[3]=fma2(h23.y,w0,a0[3]); a1[3]=fma2(h23.y,w1,a1[3]);
      a0[4]=fma2(h45.x,w0,a0[4]); a1[4]=fma2(h45.x,w1,a1[4]);
      a0[5]=fma2(h45.y,w0,a0[5]); a1[5]=fma2(h45.y,w1,a1[5]);
      a0[6]=fma2(h67.x,w0,a0[6]); a1[6]=fma2(h67.x,w1,a1[6]);
      a0[7]=fma2(h67.y,w0,a0[7]); a1[7]=fma2(h67.y,w1,a1[7]);
    }
    #pragma unroll 2
    for(int i=0;i<16;i++){
      int kp=KPS+i;
      u64 w0=wt0[i], w1=wt1[i];
      ulonglong2 h01=*(const ulonglong2*)&hsq[kp*SWH+0];
      ulonglong2 h23=*(const ulonglong2*)&hsq[kp*SWH+2];
      ulonglong2 h45=*(const ulonglong2*)&hsq[kp*SWH+4];
      ulonglong2 h67=*(const ulonglong2*)&hsq[kp*SWH+6];
      a0[0]=fma2(h01.x,w0,a0[0]); a1[0]=fma2(h01.x,w1,a1[0]);
      a0[1]=fma2(h01.y,w0,a0[1]); a1[1]=fma2(h01.y,w1,a1[1]);
      a0[2]=fma2(h23.x,w0,a0[2]); a1[2]=fma2(h23.x,w1,a1[2]);
      a0[3]=fma2(h23.y,w0,a0[3]); a1[3]=fma2(h23.y,w1,a1[3]);
      a0[4]=fma2(h45.x,w0,a0[4]); a1[4]=fma2(h45.x,w1,a1[4]);
      a0[5]=fma2(h45.y,w0,a0[5]); a1[5]=fma2(h45.y,w1,a1[5]);
      a0[6]=fma2(h67.x,w0,a0[6]); a1[6]=fma2(h67.x,w1,a1[6]);
      a0[7]=fma2(h67.y,w0,a0[7]); a1[7]=fma2(h67.y,w1,a1[7]);
    }
    #pragma unroll
    for(int r=0;r<8;r++){
      float2 p=up2(a0[r]); z[r*512+c0]=p.x+p.y+xv0[r]+b0;
      float2 q=up2(a1[r]); z[r*512+c1]=q.x+q.y+xv1[r]+b1;
    }
    __syncthreads();

    #pragma unroll
    for(int qq=0;qq<4;qq++){
      int e=tid+256*qq, r=e>>7, u=e&127;
      const float* zr=z+r*512;
      float zi=zr[u], zf=zr[128+u], zg=zr[256+u], zo=zr[384+u];
      float ig=1.f/(1.f+__expf(-zi));
      float fg=1.f/(1.f+__expf(-zf));
      zg=fminf(fmaxf(zg,-15.f),15.f);
      float eg=__expf(-2.f*zg); float gg=(1.f-eg)/(1.f+eg);
      float og=1.f/(1.f+__expf(-zo));
      float cc=fg*cs[r*H_+u]+ig*gg; cs[r*H_+u]=cc;
      float cl=fminf(fmaxf(cc,-15.f),15.f);
      float ec=__expf(-2.f*cl); float th=(1.f-ec)/(1.f+ec);
      ((float*)hsq)[(u>>1)*(2*SWH) + r*2 + (u&1)] = og*th;
    }
    __syncthreads();
  }
  #pragma unroll
  for(int qq=0;qq<4;qq++){
    int e=tid+256*qq, r=e>>7, u=e&127;
    g_x[(r0+r)*H_+u]=((float*)hsq)[(u>>1)*(2*SWH)+r*2+(u&1)];
  }
}

// ---------------- heads: 4 rows/CTA, 256 CTAs ----------------
__global__ void __launch_bounds__(512) k_head1(const float* __restrict__ Wa1,const float* __restrict__ ba1,
                                               const float* __restrict__ Wc1,const float* __restrict__ bc1){
  __shared__ float xs[4][H_];
  const int tid=threadIdx.x, half=tid>>8, j=tid&255, r0=blockIdx.x*4;
  for(int i=tid;i<4*H_;i+=512) xs[i>>7][i&127]=g_x[r0*H_+i];
  __syncthreads();
  const float* W = half? Wc1:Wa1;
  float acc[4];
  float b = half? bc1[j]:ba1[j];
  #pragma unroll
  for(int r=0;r<4;r++) acc[r]=b;
  #pragma unroll 4
  for(int k=0;k<H_;k++){
    float w=W[k*D_+j];
    #pragma unroll
    for(int r=0;r<4;r++) acc[r]+=xs[r][k]*w;
  }
  float* o = half? g_v1:g_a1;
  #pragma unroll
  for(int r=0;r<4;r++) o[(r0+r)*D_+j]=tanhf(acc[r]);
}
__global__ void __launch_bounds__(512) k_head2(const float* __restrict__ Wa2,const float* __restrict__ ba2,
                                               const float* __restrict__ Wc2,const float* __restrict__ bc2){
  __shared__ float s[2][4][D_];
  const int tid=threadIdx.x, half=tid>>8, j=tid&255, r0=blockIdx.x*4;
  for(int i=tid;i<4*D_;i+=512){
    int r=i>>8, cc=i&255;
    s[0][r][cc]=g_a1[(r0+r)*D_+cc];
    s[1][r][cc]=g_v1[(r0+r)*D_+cc];
  }
  __syncthreads();
  const float* W = half? Wc2:Wa2;
  float acc[4];
  float b = half? bc2[j]:ba2[j];
  #pragma unroll
  for(int r=0;r<4;r++) acc[r]=b;
  #pragma unroll 4
  for(int k=0;k<D_;k++){
    float w=W[k*D_+j];
    #pragma unroll
    for(int r=0;r<4;r++) acc[r]+=s[half][r][k]*w;
  }
  float* o = half? g_v2:g_a2;
  #pragma unroll
  for(int r=0;r<4;r++) o[(r0+r)*D_+j]=tanhf(acc[r]);
}
__global__ void __launch_bounds__(32) k_head3(const float* __restrict__ Wa3,const float* __restrict__ ba3,
                                              const float* __restrict__ Wc3,const float* __restrict__ bc3,
                                              const float* __restrict__ log_std, float* __restrict__ out){
  const int row=blockIdx.x, t=threadIdx.x;
  if(t<A_){
    float s=ba3[t];
    #pragma unroll 8
    for(int k=0;k<D_;k++) s+=g_a2[row*D_+k]*Wa3[k*A_+t];
    out[row*(2*A_+1)+t]=s;
  } else if(t<2*A_){
    out[row*(2*A_+1)+t]=expf(log_std[t-A_]);
  } else if(t==2*A_){
    float s=bc3[0];
    #pragma unroll 8
    for(int k=0;k<D_;k++) s+=g_v2[row*D_+k]*Wc3[k];
    out[row*(2*A_+1)+2*A_]=s;
  }
}

// ---------------------------------------------------------------------------
extern "C" void kernel_launch(void* const* d_in, const int* in_sizes, int n_in,
                              void* d_out, int out_size){
  const float* h       =(const float*)d_in[0];
  const float* Wx      =(const float*)d_in[1];
  const float* Wh      =(const float*)d_in[2];
  const float* bh      =(const float*)d_in[3];
  const float* Wa1     =(const float*)d_in[4];
  const float* ba1     =(const float*)d_in[5];
  const float* Wa2     =(const float*)d_in[6];
  const float* ba2     =(const float*)d_in[7];
  const float* Wa3     =(const float*)d_in[8];
  const float* ba3     =(const float*)d_in[9];
  const float* log_std =(const float*)d_in[10];
  const float* Wc1     =(const float*)d_in[11];
  const float* bc1     =(const float*)d_in[12];
  const float* Wc2     =(const float*)d_in[13];
  const float* bc2     =(const float*)d_in[14];
  const float* Wc3     =(const float*)d_in[15];
  const float* bc3     =(const float*)d_in[16];
  float* out=(float*)d_out;

  const int smK1 = 4*128*SA*2;                                   // 139264 B
  const int smLS = KPS*512*8 + 8*512*4 + 64*SWH*8 + 8*128*4;     // 222208 B
  cudaFuncSetAttribute(k_xg_mma, cudaFuncAttributeMaxDynamicSharedMemorySize, smK1);
  cudaFuncSetAttribute(k_lstm,   cudaFuncAttributeMaxDynamicSharedMemorySize, smLS);

  dim3 g1((B_*T_)/128, G4H/128);                  // (2048, 4)
  k_xg_mma<<<g1, 256, smK1>>>(h, Wx);
  k_lstm<<<B_/8, 256, smLS>>>(Wh, bh);            // 128 CTAs
  k_head1<<<B_/4, 512>>>(Wa1, ba1, Wc1, bc1);
  k_head2<<<B_/4, 512>>>(Wa2, ba2, Wc2, bc2);
  k_head3<<<B_, 32>>>(Wa3, ba3, Wc3, bc3, log_std, out);
}

// round 14
// speedup vs baseline: 1.5748x; 1.5748x over previous
#include <cuda_runtime.h>
#include <cuda_bf16.h>
#include <math.h>
#include <stdint.h>

#define B_ 1024
#define T_ 256
#define F_ 128
#define H_ 128
#define G4H 512
#define D_ 256
#define A_ 8

__device__ float g_xg[(size_t)B_*T_*G4H];
__device__ float g_x[B_*H_];
__device__ float g_a1[B_*D_]; __device__ float g_v1[B_*D_];
__device__ float g_a2[B_*D_]; __device__ float g_v2[B_*D_];

// ---------------- helpers ----------------
__device__ __forceinline__ uint32_t s2u(const void* p){
  uint32_t a; asm("{ .reg .u64 t; cvta.to.shared.u64 t, %1; cvt.u32.u64 %0, t; }":"=r"(a):"l"(p)); return a;
}
__device__ __forceinline__ void ldsm4(uint32_t* r, uint32_t a){
  asm volatile("ldmatrix.sync.aligned.m8n8.x4.shared.b16 {%0,%1,%2,%3},[%4];"
    :"=r"(r[0]),"=r"(r[1]),"=r"(r[2]),"=r"(r[3]):"r"(a));
}
__device__ __forceinline__ void ldsm2t(uint32_t* r, uint32_t a){
  asm volatile("ldmatrix.sync.aligned.m8n8.x2.trans.shared.b16 {%0,%1},[%2];"
    :"=r"(r[0]),"=r"(r[1]):"r"(a));
}
__device__ __forceinline__ void mma16816(float* d, const uint32_t* a, const uint32_t* b){
  asm volatile("mma.sync.aligned.m16n8k16.row.col.f32.bf16.bf16.f32 "
    "{%0,%1,%2,%3},{%4,%5,%6,%7},{%8,%9},{%0,%1,%2,%3};"
    :"+f"(d[0]),"+f"(d[1]),"+f"(d[2]),"+f"(d[3])
    :"r"(a[0]),"r"(a[1]),"r"(a[2]),"r"(a[3]),"r"(b[0]),"r"(b[1]));
}
__device__ __forceinline__ float b2f(__nv_bfloat16 x){ return __bfloat162float(x); }
__device__ __forceinline__ void splitst(float4 v, __nv_bfloat16* Hs, __nv_bfloat16* Ls){
  __nv_bfloat16 h0=__float2bfloat16_rn(v.x);
  __nv_bfloat16 h1=__float2bfloat16_rn(v.y);
  __nv_bfloat16 h2=__float2bfloat16_rn(v.z);
  __nv_bfloat16 h3=__float2bfloat16_rn(v.w);
  __nv_bfloat16 l0=__float2bfloat16_rn(v.x-b2f(h0));
  __nv_bfloat16 l1=__float2bfloat16_rn(v.y-b2f(h1));
  __nv_bfloat16 l2=__float2bfloat16_rn(v.z-b2f(h2));
  __nv_bfloat16 l3=__float2bfloat16_rn(v.w-b2f(h3));
  *(__nv_bfloat162*)(Hs)  =__halves2bfloat162(h0,h1);
  *(__nv_bfloat162*)(Hs+2)=__halves2bfloat162(h2,h3);
  *(__nv_bfloat162*)(Ls)  =__halves2bfloat162(l0,l1);
  *(__nv_bfloat162*)(Ls+2)=__halves2bfloat162(l2,l3);
}

// ---------------- K1: xg = h @ Wx, bf16 hi/lo split mma (proven) -----------
#define SA 136
__global__ void __launch_bounds__(256,1) k_xg_mma(const float* __restrict__ hin,
                                                  const float* __restrict__ Wx){
  extern __shared__ __align__(16) char smraw[];
  __nv_bfloat16 *Ah=(__nv_bfloat16*)smraw, *Al=Ah+128*SA, *Bh=Al+128*SA, *Bl=Bh+128*SA;
  const int tid=threadIdx.x, lane=tid&31, wid=tid>>5;
  const int m0=blockIdx.x*128, n0=blockIdx.y*128;

  #pragma unroll
  for(int i=0;i<16;i++){
    int idx=i*256+tid, row=idx>>5, c4=(idx&31)<<2;
    float4 a=*(const float4*)&hin[(size_t)(m0+row)*F_+c4];
    float4 b=*(const float4*)&Wx[(size_t)row*G4H+n0+c4];
    splitst(a, Ah+row*SA+c4, Al+row*SA+c4);
    splitst(b, Bh+row*SA+c4, Bl+row*SA+c4);
  }
  __syncthreads();

  const int wm=(wid>>2)*64, wn=(wid&3)*32;
  float acc[16][4];
  #pragma unroll
  for(int i=0;i<16;i++){acc[i][0]=0.f;acc[i][1]=0.f;acc[i][2]=0.f;acc[i][3]=0.f;}

  #pragma unroll
  for(int ks=0;ks<8;ks++){
    int k0=ks*16;
    uint32_t ah[4][4], al[4][4], bh[4][2], bl[4][2];
    int ar=lane&15, ac=k0+((lane>>4)<<3);
    #pragma unroll
    for(int mi=0;mi<4;mi++){
      ldsm4(ah[mi], s2u(Ah+(wm+mi*16+ar)*SA+ac));
      ldsm4(al[mi], s2u(Al+(wm+mi*16+ar)*SA+ac));
    }
    int br=k0+(lane&15);
    #pragma unroll
    for(int ni=0;ni<4;ni++){
      ldsm2t(bh[ni], s2u(Bh+br*SA+wn+ni*8));
      ldsm2t(bl[ni], s2u(Bl+br*SA+wn+ni*8));
    }
    #pragma unroll
    for(int mi=0;mi<4;mi++)
      #pragma unroll
      for(int ni=0;ni<4;ni++){
        float* d=acc[mi*4+ni];
        mma16816(d, ah[mi], bh[ni]);
        mma16816(d, ah[mi], bl[ni]);
        mma16816(d, al[mi], bh[ni]);
      }
  }
  int r=lane>>2, c2=(lane&3)*2;
  #pragma unroll
  for(int mi=0;mi<4;mi++)
    #pragma unroll
    for(int ni=0;ni<4;ni++){
      float* d=acc[mi*4+ni];
      size_t base=(size_t)(m0+wm+mi*16+r)*G4H + n0+wn+ni*8+c2;
      *(float2*)&g_xg[base]        =make_float2(d[0],d[1]);
      *(float2*)&g_xg[base+8*G4H]  =make_float2(d[2],d[3]);
    }
}

// ---------------- K2: tensor-core LSTM -------------------------------------
// BM=16 rows/CTA, 64 CTAs, 256 thr (8 warps x 64 cols).
// z = hsH@WhH + hsL@WhH + hsH@WhL   (bf16 hi/lo split, fp32 acc)
// WhH fragments live in registers (loaded once); WhL in smem (overwrite trick).
#define SB 520      // WhS row stride (bf16 elems)
#define ZS 516      // z row stride (f32)
#define HS 136      // hs row stride (bf16)
__global__ void __launch_bounds__(256,1) k_lstm(const float* __restrict__ Wh,
                                                const float* __restrict__ bh){
  extern __shared__ __align__(16) char smraw[];
  __nv_bfloat16* WhS=(__nv_bfloat16*)smraw;                 // [128][SB]
  float*         z  =(float*)(smraw + 128*SB*2);            // [16][ZS]
  __nv_bfloat16* hsH=(__nv_bfloat16*)((char*)z + 16*ZS*4);  // [16][HS]
  __nv_bfloat16* hsL=hsH + 16*HS;                           // [16][HS]

  const int tid=threadIdx.x, lane=tid&31, wid=tid>>5;
  const int r0=blockIdx.x*16;
  const int wn=wid*64;
  const int kk=tid&127, brow=tid>>7;   // gate cell: col kk, rows brow+2q

  // ---- stage Wh HI into smem (bf16) ----
  for(int i=tid;i<32768;i+=256){
    int k=i>>8, n2=(i&255)<<1;
    float2 v=((const float2*)Wh)[i];
    *(__nv_bfloat162*)&WhS[k*SB+n2]=
      __halves2bfloat162(__float2bfloat16_rn(v.x), __float2bfloat16_rn(v.y));
  }
  __syncthreads();

  // ---- load B-hi fragments into registers (time-invariant) ----
  uint32_t bhr[128];
  {
    int br=lane&15;
    #pragma unroll
    for(int ks=0;ks<8;ks++)
      #pragma unroll
      for(int nt=0;nt<8;nt++)
        ldsm2t(&bhr[(ks*8+nt)*2], s2u(WhS + (ks*16+br)*SB + wn + nt*8));
  }
  __syncthreads();

  // ---- overwrite smem with Wh LO ----
  for(int i=tid;i<32768;i+=256){
    int k=i>>8, n2=(i&255)<<1;
    float2 v=((const float2*)Wh)[i];
    __nv_bfloat16 hx=__float2bfloat16_rn(v.x), hy=__float2bfloat16_rn(v.y);
    *(__nv_bfloat162*)&WhS[k*SB+n2]=
      __halves2bfloat162(__float2bfloat16_rn(v.x-b2f(hx)),
                         __float2bfloat16_rn(v.y-b2f(hy)));
  }
  // zero hs hi/lo (incl pad)
  for(int i=tid;i<16*HS;i+=256){ hsH[i]=__float2bfloat16_rn(0.f); hsL[i]=__float2bfloat16_rn(0.f); }
  float creg[8];
  #pragma unroll
  for(int q=0;q<8;q++) creg[q]=0.f;
  const float bi=bh[kk], bf_=bh[128+kk], bg=bh[256+kk], bo=bh[384+kk];
  const float* xbase = g_xg + (size_t)(r0+brow)*T_*G4H + kk;
  __syncthreads();

  for(int t=0;t<T_;t++){
    // stage xg for the gate phase (consumed ~3k cyc later)
    float xi[8], xf[8], xg[8], xo[8];
    #pragma unroll
    for(int q=0;q<8;q++){
      const float* p = xbase + (size_t)q*(2*T_*G4H) + (size_t)t*G4H;
      xi[q]=p[0]; xf[q]=p[128]; xg[q]=p[256]; xo[q]=p[384];
    }

    float acc[8][4];
    #pragma unroll
    for(int i=0;i<8;i++){acc[i][0]=0.f;acc[i][1]=0.f;acc[i][2]=0.f;acc[i][3]=0.f;}

    #pragma unroll
    for(int ks=0;ks<8;ks++){
      int k0=ks*16;
      uint32_t ah[4], al[4], bl[2];
      int ar=lane&15, ac=k0+((lane>>4)<<3);
      ldsm4(ah, s2u(hsH + ar*HS + ac));
      ldsm4(al, s2u(hsL + ar*HS + ac));
      int br=k0+(lane&15);
      #pragma unroll
      for(int nt=0;nt<8;nt++){
        ldsm2t(bl, s2u(WhS + br*SB + wn + nt*8));
        const uint32_t* bh2=&bhr[(ks*8+nt)*2];
        mma16816(acc[nt], ah, bh2);
        mma16816(acc[nt], al, bh2);
        mma16816(acc[nt], ah, bl);
      }
    }
    // write z
    {
      int zr=lane>>2, zc=(lane&3)*2;
      #pragma unroll
      for(int nt=0;nt<8;nt++){
        int col=wn+nt*8+zc;
        *(float2*)&z[zr*ZS+col]    =make_float2(acc[nt][0],acc[nt][1]);
        *(float2*)&z[(zr+8)*ZS+col]=make_float2(acc[nt][2],acc[nt][3]);
      }
    }
    __syncthreads();

    // gates: 8 cells/thread (rows brow+2q, col kk)
    #pragma unroll
    for(int q=0;q<8;q++){
      int rr=brow+2*q;
      const float* zr=z+rr*ZS;
      float zi=zr[kk]     +xi[q]+bi;
      float zf=zr[128+kk] +xf[q]+bf_;
      float zg=zr[256+kk] +xg[q]+bg;
      float zo=zr[384+kk] +xo[q]+bo;
      float ig=__fdividef(1.f,1.f+__expf(-zi));
      float fg=__fdividef(1.f,1.f+__expf(-zf));
      float zgc=fminf(fmaxf(zg,-15.f),15.f);
      float eg=__expf(-2.f*zgc);
      float gg=__fdividef(1.f-eg,1.f+eg);
      float og=__fdividef(1.f,1.f+__expf(-zo));
      float cc=fg*creg[q]+ig*gg; creg[q]=cc;
      float ccl=fminf(fmaxf(cc,-15.f),15.f);
      float ec=__expf(-2.f*ccl);
      float th=__fdividef(1.f-ec,1.f+ec);
      float hv=og*th;
      __nv_bfloat16 hh=__float2bfloat16_rn(hv);
      hsH[rr*HS+kk]=hh;
      hsL[rr*HS+kk]=__float2bfloat16_rn(hv-b2f(hh));
      if(t==T_-1) g_x[(r0+rr)*H_+kk]=hv;
    }
    __syncthreads();
  }
}

// ---------------- heads: 4 rows/CTA, 256 CTAs ----------------
__global__ void __launch_bounds__(512) k_head1(const float* __restrict__ Wa1,const float* __restrict__ ba1,
                                               const float* __restrict__ Wc1,const float* __restrict__ bc1){
  __shared__ float xs[4][H_];
  const int tid=threadIdx.x, half=tid>>8, j=tid&255, r0=blockIdx.x*4;
  for(int i=tid;i<4*H_;i+=512) xs[i>>7][i&127]=g_x[r0*H_+i];
  __syncthreads();
  const float* W = half? Wc1:Wa1;
  float acc[4];
  float b = half? bc1[j]:ba1[j];
  #pragma unroll
  for(int r=0;r<4;r++) acc[r]=b;
  #pragma unroll 4
  for(int k=0;k<H_;k++){
    float w=W[k*D_+j];
    #pragma unroll
    for(int r=0;r<4;r++) acc[r]+=xs[r][k]*w;
  }
  float* o = half? g_v1:g_a1;
  #pragma unroll
  for(int r=0;r<4;r++) o[(r0+r)*D_+j]=tanhf(acc[r]);
}
__global__ void __launch_bounds__(512) k_head2(const float* __restrict__ Wa2,const float* __restrict__ ba2,
                                               const float* __restrict__ Wc2,const float* __restrict__ bc2){
  __shared__ float s[2][4][D_];
  const int tid=threadIdx.x, half=tid>>8, j=tid&255, r0=blockIdx.x*4;
  for(int i=tid;i<4*D_;i+=512){
    int r=i>>8, cc=i&255;
    s[0][r][cc]=g_a1[(r0+r)*D_+cc];
    s[1][r][cc]=g_v1[(r0+r)*D_+cc];
  }
  __syncthreads();
  const float* W = half? Wc2:Wa2;
  float acc[4];
  float b = half? bc2[j]:ba2[j];
  #pragma unroll
  for(int r=0;r<4;r++) acc[r]=b;
  #pragma unroll 4
  for(int k=0;k<D_;k++){
    float w=W[k*D_+j];
    #pragma unroll
    for(int r=0;r<4;r++) acc[r]+=s[half][r][k]*w;
  }
  float* o = half? g_v2:g_a2;
  #pragma unroll
  for(int r=0;r<4;r++) o[(r0+r)*D_+j]=tanhf(acc[r]);
}
__global__ void __launch_bounds__(32) k_head3(const float* __restrict__ Wa3,const float* __restrict__ ba3,
                                              const float* __restrict__ Wc3,const float* __restrict__ bc3,
                                              const float* __restrict__ log_std, float* __restrict__ out){
  const int row=blockIdx.x, t=threadIdx.x;
  if(t<A_){
    float s=ba3[t];
    #pragma unroll 8
    for(int k=0;k<D_;k++) s+=g_a2[row*D_+k]*Wa3[k*A_+t];
    out[row*(2*A_+1)+t]=s;
  } else if(t<2*A_){
    out[row*(2*A_+1)+t]=expf(log_std[t-A_]);
  } else if(t==2*A_){
    float s=bc3[0];
    #pragma unroll 8
    for(int k=0;k<D_;k++) s+=g_v2[row*D_+k]*Wc3[k];
    out[row*(2*A_+1)+2*A_]=s;
  }
}

// ---------------------------------------------------------------------------
extern "C" void kernel_launch(void* const* d_in, const int* in_sizes, int n_in,
                              void* d_out, int out_size){
  const float* h       =(const float*)d_in[0];
  const float* Wx      =(const float*)d_in[1];
  const float* Wh      =(const float*)d_in[2];
  const float* bh      =(const float*)d_in[3];
  const float* Wa1     =(const float*)d_in[4];
  const float* ba1     =(const float*)d_in[5];
  const float* Wa2     =(const float*)d_in[6];
  const float* ba2     =(const float*)d_in[7];
  const float* Wa3     =(const float*)d_in[8];
  const float* ba3     =(const float*)d_in[9];
  const float* log_std =(const float*)d_in[10];
  const float* Wc1     =(const float*)d_in[11];
  const float* bc1     =(const float*)d_in[12];
  const float* Wc2     =(const float*)d_in[13];
  const float* bc2     =(const float*)d_in[14];
  const float* Wc3     =(const float*)d_in[15];
  const float* bc3     =(const float*)d_in[16];
  float* out=(float*)d_out;

  const int smK1 = 4*128*SA*2;                              // 139264 B
  const int smLS = 128*SB*2 + 16*ZS*4 + 2*16*HS*2;          // 174848 B
  cudaFuncSetAttribute(k_xg_mma, cudaFuncAttributeMaxDynamicSharedMemorySize, smK1);
  cudaFuncSetAttribute(k_lstm,   cudaFuncAttributeMaxDynamicSharedMemorySize, smLS);

  dim3 g1((B_*T_)/128, G4H/128);                  // (2048, 4)
  k_xg_mma<<<g1, 256, smK1>>>(h, Wx);
  k_lstm<<<B_/16, 256, smLS>>>(Wh, bh);           // 64 CTAs
  k_head1<<<B_/4, 512>>>(Wa1, ba1, Wc1, bc1);
  k_head2<<<B_/4, 512>>>(Wa2, ba2, Wc2, bc2);
  k_head3<<<B_, 32>>>(Wa3, ba3, Wc3, bc3, log_std, out);
}

// round 16
// speedup vs baseline: 1.8484x; 1.1738x over previous
#include <cuda_runtime.h>
#include <cuda_bf16.h>
#include <math.h>
#include <stdint.h>

#define B_ 1024
#define T_ 256
#define F_ 128
#define H_ 128
#define G4H 512
#define D_ 256
#define A_ 8

__device__ float g_xg[(size_t)B_*T_*G4H];
__device__ float g_x[B_*H_];
__device__ float g_a1[B_*D_]; __device__ float g_v1[B_*D_];
__device__ float g_a2[B_*D_]; __device__ float g_v2[B_*D_];

// ---------------- helpers ----------------
__device__ __forceinline__ uint32_t s2u(const void* p){
  uint32_t a; asm("{ .reg .u64 t; cvta.to.shared.u64 t, %1; cvt.u32.u64 %0, t; }":"=r"(a):"l"(p)); return a;
}
__device__ __forceinline__ uint32_t ctarank(){
  uint32_t r; asm("mov.u32 %0, %%cluster_ctarank;":"=r"(r)); return r;
}
__device__ __forceinline__ uint32_t mapa_u32(uint32_t addr, uint32_t rank){
  uint32_t r; asm("mapa.shared::cluster.u32 %0,%1,%2;":"=r"(r):"r"(addr),"r"(rank)); return r;
}
__device__ __forceinline__ void st_cluster_b16(uint32_t addr, unsigned short v){
  asm volatile("st.shared::cluster.b16 [%0],%1;"::"r"(addr),"h"(v):"memory");
}
#define CLUSTER_ARRIVE() asm volatile("barrier.cluster.arrive.aligned;" ::: "memory")
#define CLUSTER_WAIT()   asm volatile("barrier.cluster.wait.aligned;" ::: "memory")
__device__ __forceinline__ void ldsm4(uint32_t* r, uint32_t a){
  asm volatile("ldmatrix.sync.aligned.m8n8.x4.shared.b16 {%0,%1,%2,%3},[%4];"
    :"=r"(r[0]),"=r"(r[1]),"=r"(r[2]),"=r"(r[3]):"r"(a));
}
__device__ __forceinline__ void ldsm2t(uint32_t* r, uint32_t a){
  asm volatile("ldmatrix.sync.aligned.m8n8.x2.trans.shared.b16 {%0,%1},[%2];"
    :"=r"(r[0]),"=r"(r[1]):"r"(a));
}
__device__ __forceinline__ void mma16816(float* d, const uint32_t* a, const uint32_t* b){
  asm volatile("mma.sync.aligned.m16n8k16.row.col.f32.bf16.bf16.f32 "
    "{%0,%1,%2,%3},{%4,%5,%6,%7},{%8,%9},{%0,%1,%2,%3};"
    :"+f"(d[0]),"+f"(d[1]),"+f"(d[2]),"+f"(d[3])
    :"r"(a[0]),"r"(a[1]),"r"(a[2]),"r"(a[3]),"r"(b[0]),"r"(b[1]));
}
__device__ __forceinline__ float b2f(__nv_bfloat16 x){ return __bfloat162float(x); }
__device__ __forceinline__ void splitst(float4 v, __nv_bfloat16* Hs, __nv_bfloat16* Ls){
  __nv_bfloat16 h0=__float2bfloat16_rn(v.x);
  __nv_bfloat16 h1=__float2bfloat16_rn(v.y);
  __nv_bfloat16 h2=__float2bfloat16_rn(v.z);
  __nv_bfloat16 h3=__float2bfloat16_rn(v.w);
  __nv_bfloat16 l0=__float2bfloat16_rn(v.x-b2f(h0));
  __nv_bfloat16 l1=__float2bfloat16_rn(v.y-b2f(h1));
  __nv_bfloat16 l2=__float2bfloat16_rn(v.z-b2f(h2));
  __nv_bfloat16 l3=__float2bfloat16_rn(v.w-b2f(h3));
  *(__nv_bfloat162*)(Hs)  =__halves2bfloat162(h0,h1);
  *(__nv_bfloat162*)(Hs+2)=__halves2bfloat162(h2,h3);
  *(__nv_bfloat162*)(Ls)  =__halves2bfloat162(l0,l1);
  *(__nv_bfloat162*)(Ls+2)=__halves2bfloat162(l2,l3);
}

// ---------------- K1: xg = h @ Wx, bf16 hi/lo split mma (proven) -----------
#define SA 136
__global__ void __launch_bounds__(256,1) k_xg_mma(const float* __restrict__ hin,
                                                  const float* __restrict__ Wx){
  extern __shared__ __align__(16) char smraw[];
  __nv_bfloat16 *Ah=(__nv_bfloat16*)smraw, *Al=Ah+128*SA, *Bh=Al+128*SA, *Bl=Bh+128*SA;
  const int tid=threadIdx.x, lane=tid&31, wid=tid>>5;
  const int m0=blockIdx.x*128, n0=blockIdx.y*128;

  #pragma unroll
  for(int i=0;i<16;i++){
    int idx=i*256+tid, row=idx>>5, c4=(idx&31)<<2;
    float4 a=*(const float4*)&hin[(size_t)(m0+row)*F_+c4];
    float4 b=*(const float4*)&Wx[(size_t)row*G4H+n0+c4];
    splitst(a, Ah+row*SA+c4, Al+row*SA+c4);
    splitst(b, Bh+row*SA+c4, Bl+row*SA+c4);
  }
  __syncthreads();

  const int wm=(wid>>2)*64, wn=(wid&3)*32;
  float acc[16][4];
  #pragma unroll
  for(int i=0;i<16;i++){acc[i][0]=0.f;acc[i][1]=0.f;acc[i][2]=0.f;acc[i][3]=0.f;}

  #pragma unroll
  for(int ks=0;ks<8;ks++){
    int k0=ks*16;
    uint32_t ah[4][4], al[4][4], bh[4][2], bl[4][2];
    int ar=lane&15, ac=k0+((lane>>4)<<3);
    #pragma unroll
    for(int mi=0;mi<4;mi++){
      ldsm4(ah[mi], s2u(Ah+(wm+mi*16+ar)*SA+ac));
      ldsm4(al[mi], s2u(Al+(wm+mi*16+ar)*SA+ac));
    }
    int br=k0+(lane&15);
    #pragma unroll
    for(int ni=0;ni<4;ni++){
      ldsm2t(bh[ni], s2u(Bh+br*SA+wn+ni*8));
      ldsm2t(bl[ni], s2u(Bl+br*SA+wn+ni*8));
    }
    #pragma unroll
    for(int mi=0;mi<4;mi++)
      #pragma unroll
      for(int ni=0;ni<4;ni++){
        float* d=acc[mi*4+ni];
        mma16816(d, ah[mi], bh[ni]);
        mma16816(d, ah[mi], bl[ni]);
        mma16816(d, al[mi], bh[ni]);
      }
  }
  int r=lane>>2, c2=(lane&3)*2;
  #pragma unroll
  for(int mi=0;mi<4;mi++)
    #pragma unroll
    for(int ni=0;ni<4;ni++){
      float* d=acc[mi*4+ni];
      size_t base=(size_t)(m0+wm+mi*16+r)*G4H + n0+wn+ni*8+c2;
      *(float2*)&g_xg[base]        =make_float2(d[0],d[1]);
      *(float2*)&g_xg[base+8*G4H]  =make_float2(d[2],d[3]);
    }
}

// ---------------- K2: cluster-split tensor-core LSTM -----------------------
// 2-CTA cluster per 16 batch rows; rank r owns k in [64r,64r+64).
// Each CTA: z for its 256 cols (4 gates x 64), gates for its 64 k's,
// pushes hs hi/lo slice to peer smem; 2 cluster barriers/step.
#define SBc 264     // WhS row stride (bf16)
#define ZS2 260     // z row stride (f32)
#define HS 136      // hs row stride (bf16)
__global__ void __launch_bounds__(256,1) __cluster_dims__(2,1,1)
k_lstm(const float* __restrict__ Wh, const float* __restrict__ bh){
  extern __shared__ __align__(16) char smraw[];
  __nv_bfloat16* WhS=(__nv_bfloat16*)smraw;                 // [128][SBc]
  float*         z  =(float*)(smraw + 128*SBc*2);           // [16][ZS2]
  __nv_bfloat16* hsH=(__nv_bfloat16*)((char*)z + 16*ZS2*4); // [16][HS]
  __nv_bfloat16* hsL=hsH + 16*HS;                           // [16][HS]

  const int tid=threadIdx.x, lane=tid&31, wid=tid>>5;
  const uint32_t rank=ctarank(), peer=rank^1;
  const int r0=(blockIdx.x>>1)*16;
  const int n0=rank*64;
  const int wn=wid*32;                 // warp's 32 cols of the 256
  const int kk2=tid&63, rgrp=tid>>6;   // gate cell: col kk2, rows rgrp+4q

  // ---- stage Wh HI (this CTA's 256 columns) ----
  for(int i=tid;i<128*256;i+=256){
    int k=i>>8, idx=i&255, g=idx>>6, c=idx&63;
    WhS[k*SBc+idx]=__float2bfloat16_rn(Wh[(size_t)k*G4H + g*128 + n0 + c]);
  }
  __syncthreads();
  // ---- B-hi fragments into registers (time-invariant): 8ks x 4nt ----
  uint32_t bhr[64];
  {
    int br=lane&15;
    #pragma unroll
    for(int ks=0;ks<8;ks++)
      #pragma unroll
      for(int nt=0;nt<4;nt++)
        ldsm2t(&bhr[(ks*4+nt)*2], s2u(WhS + (ks*16+br)*SBc + wn + nt*8));
  }
  __syncthreads();
  // ---- overwrite smem with Wh LO ----
  for(int i=tid;i<128*256;i+=256){
    int k=i>>8, idx=i&255, g=idx>>6, c=idx&63;
    float v=Wh[(size_t)k*G4H + g*128 + n0 + c];
    __nv_bfloat16 hx=__float2bfloat16_rn(v);
    WhS[k*SBc+idx]=__float2bfloat16_rn(v-b2f(hx));
  }
  for(int i=tid;i<16*HS;i+=256){ hsH[i]=__float2bfloat16_rn(0.f); hsL[i]=__float2bfloat16_rn(0.f); }
  float creg[4];
  #pragma unroll
  for(int q=0;q<4;q++) creg[q]=0.f;
  const float bi=bh[n0+kk2], bf_=bh[128+n0+kk2], bg=bh[256+n0+kk2], bo=bh[384+n0+kk2];
  const uint32_t peerH=mapa_u32(s2u(hsH), peer), peerL=mapa_u32(s2u(hsL), peer);
  __syncthreads();
  CLUSTER_ARRIVE(); CLUSTER_WAIT();

  for(int t=0;t<T_;t++){
    // stage xg (consumed in gate phase)
    float xi[4], xf[4], xgv[4], xo[4];
    #pragma unroll
    for(int q=0;q<4;q++){
      const float* p=g_xg + ((size_t)(r0+rgrp+4*q)*T_+t)*G4H;
      xi[q]=p[n0+kk2]; xf[q]=p[128+n0+kk2]; xgv[q]=p[256+n0+kk2]; xo[q]=p[384+n0+kk2];
    }

    float acc[4][4];
    #pragma unroll
    for(int i=0;i<4;i++){acc[i][0]=0.f;acc[i][1]=0.f;acc[i][2]=0.f;acc[i][3]=0.f;}

    #pragma unroll
    for(int ks=0;ks<8;ks++){
      int k0=ks*16;
      uint32_t ah[4], al[4], bl[2];
      int ar=lane&15, ac=k0+((lane>>4)<<3);
      ldsm4(ah, s2u(hsH + ar*HS + ac));
      ldsm4(al, s2u(hsL + ar*HS + ac));
      int br=k0+(lane&15);
      #pragma unroll
      for(int nt=0;nt<4;nt++){
        ldsm2t(bl, s2u(WhS + br*SBc + wn + nt*8));
        const uint32_t* b2=&bhr[(ks*4+nt)*2];
        mma16816(acc[nt], ah, b2);
        mma16816(acc[nt], al, b2);
        mma16816(acc[nt], ah, bl);
      }
    }
    // write z (local)
    {
      int zr=lane>>2, zc=(lane&3)*2;
      #pragma unroll
      for(int nt=0;nt<4;nt++){
        int col=wn+nt*8+zc;
        *(float2*)&z[zr*ZS2+col]    =make_float2(acc[nt][0],acc[nt][1]);
        *(float2*)&z[(zr+8)*ZS2+col]=make_float2(acc[nt][2],acc[nt][3]);
      }
    }
    __syncthreads();          // z visible; all warps done reading hs
    CLUSTER_ARRIVE();         // signal: done reading my hs (peer may store into it)

    // gates: 4 cells/thread (rows rgrp+4q, col kk2)
    float hv[4];
    #pragma unroll
    for(int q=0;q<4;q++){
      int rr=rgrp+4*q;
      const float* zr=z+rr*ZS2;
      float zi=zr[kk2]      +xi[q] +bi;
      float zf=zr[64+kk2]   +xf[q] +bf_;
      float zg=zr[128+kk2]  +xgv[q]+bg;
      float zo=zr[192+kk2]  +xo[q] +bo;
      float ig=__fdividef(1.f,1.f+__expf(-zi));
      float fg=__fdividef(1.f,1.f+__expf(-zf));
      float zgc=fminf(fmaxf(zg,-15.f),15.f);
      float eg=__expf(-2.f*zgc);
      float gg=__fdividef(1.f-eg,1.f+eg);
      float og=__fdividef(1.f,1.f+__expf(-zo));
      float cc=fg*creg[q]+ig*gg; creg[q]=cc;
      float ccl=fminf(fmaxf(cc,-15.f),15.f);
      float ec=__expf(-2.f*ccl);
      hv[q]=og*__fdividef(1.f-ec,1.f+ec);
    }
    CLUSTER_WAIT();           // peer done reading its hs -> safe to store

    #pragma unroll
    for(int q=0;q<4;q++){
      int rr=rgrp+4*q;
      __nv_bfloat16 hh=__float2bfloat16_rn(hv[q]);
      __nv_bfloat16 hl=__float2bfloat16_rn(hv[q]-b2f(hh));
      int off=rr*HS + n0 + kk2;
      hsH[off]=hh; hsL[off]=hl;
      st_cluster_b16(peerH + off*2, *(unsigned short*)&hh);
      st_cluster_b16(peerL + off*2, *(unsigned short*)&hl);
      if(t==T_-1) g_x[(r0+rr)*H_ + n0 + kk2]=hv[q];
    }
    CLUSTER_ARRIVE(); CLUSTER_WAIT();   // all hs stores visible cluster-wide
  }
}

// ---------------- heads: 4 rows/CTA, 256 CTAs ----------------
__global__ void __launch_bounds__(512) k_head1(const float* __restrict__ Wa1,const float* __restrict__ ba1,
                                               const float* __restrict__ Wc1,const float* __restrict__ bc1){
  __shared__ float xs[4][H_];
  const int tid=threadIdx.x, half=tid>>8, j=tid&255, r0=blockIdx.x*4;
  for(int i=tid;i<4*H_;i+=512) xs[i>>7][i&127]=g_x[r0*H_+i];
  __syncthreads();
  const float* W = half? Wc1:Wa1;
  float acc[4];
  float b = half? bc1[j]:ba1[j];
  #pragma unroll
  for(int r=0;r<4;r++) acc[r]=b;
  #pragma unroll 4
  for(int k=0;k<H_;k++){
    float w=W[k*D_+j];
    #pragma unroll
    for(int r=0;r<4;r++) acc[r]+=xs[r][k]*w;
  }
  float* o = half? g_v1:g_a1;
  #pragma unroll
  for(int r=0;r<4;r++) o[(r0+r)*D_+j]=tanhf(acc[r]);
}
__global__ void __launch_bounds__(512) k_head2(const float* __restrict__ Wa2,const float* __restrict__ ba2,
                                               const float* __restrict__ Wc2,const float* __restrict__ bc2){
  __shared__ float s[2][4][D_];
  const int tid=threadIdx.x, half=tid>>8, j=tid&255, r0=blockIdx.x*4;
  for(int i=tid;i<4*D_;i+=512){
    int r=i>>8, cc=i&255;
    s[0][r][cc]=g_a1[(r0+r)*D_+cc];
    s[1][r][cc]=g_v1[(r0+r)*D_+cc];
  }
  __syncthreads();
  const float* W = half? Wc2:Wa2;
  float acc[4];
  float b = half? bc2[j]:ba2[j];
  #pragma unroll
  for(int r=0;r<4;r++) acc[r]=b;
  #pragma unroll 4
  for(int k=0;k<D_;k++){
    float w=W[k*D_+j];
    #pragma unroll
    for(int r=0;r<4;r++) acc[r]+=s[half][r][k]*w;
  }
  float* o = half? g_v2:g_a2;
  #pragma unroll
  for(int r=0;r<4;r++) o[(r0+r)*D_+j]=tanhf(acc[r]);
}
__global__ void __launch_bounds__(32) k_head3(const float* __restrict__ Wa3,const float* __restrict__ ba3,
                                              const float* __restrict__ Wc3,const float* __restrict__ bc3,
                                              const float* __restrict__ log_std, float* __restrict__ out){
  const int row=blockIdx.x, t=threadIdx.x;
  if(t<A_){
    float s=ba3[t];
    #pragma unroll 8
    for(int k=0;k<D_;k++) s+=g_a2[row*D_+k]*Wa3[k*A_+t];
    out[row*(2*A_+1)+t]=s;
  } else if(t<2*A_){
    out[row*(2*A_+1)+t]=expf(log_std[t-A_]);
  } else if(t==2*A_){
    float s=bc3[0];
    #pragma unroll 8
    for(int k=0;k<D_;k++) s+=g_v2[row*D_+k]*Wc3[k];
    out[row*(2*A_+1)+2*A_]=s;
  }
}

// ---------------------------------------------------------------------------
extern "C" void kernel_launch(void* const* d_in, const int* in_sizes, int n_in,
                              void* d_out, int out_size){
  const float* h       =(const float*)d_in[0];
  const float* Wx      =(const float*)d_in[1];
  const float* Wh      =(const float*)d_in[2];
  const float* bh      =(const float*)d_in[3];
  const float* Wa1     =(const float*)d_in[4];
  const float* ba1     =(const float*)d_in[5];
  const float* Wa2     =(const float*)d_in[6];
  const float* ba2     =(const float*)d_in[7];
  const float* Wa3     =(const float*)d_in[8];
  const float* ba3     =(const float*)d_in[9];
  const float* log_std =(const float*)d_in[10];
  const float* Wc1     =(const float*)d_in[11];
  const float* bc1     =(const float*)d_in[12];
  const float* Wc2     =(const float*)d_in[13];
  const float* bc2     =(const float*)d_in[14];
  const float* Wc3     =(const float*)d_in[15];
  const float* bc3     =(const float*)d_in[16];
  float* out=(float*)d_out;

  const int smK1 = 4*128*SA*2;                              // 139264 B
  const int smLS = 128*SBc*2 + 16*ZS2*4 + 2*16*HS*2;        // 92928 B
  cudaFuncSetAttribute(k_xg_mma, cudaFuncAttributeMaxDynamicSharedMemorySize, smK1);
  cudaFuncSetAttribute(k_lstm,   cudaFuncAttributeMaxDynamicSharedMemorySize, smLS);

  dim3 g1((B_*T_)/128, G4H/128);                  // (2048, 4)
  k_xg_mma<<<g1, 256, smK1>>>(h, Wx);
  k_lstm<<<B_/8, 256, smLS>>>(Wh, bh);            // 128 CTAs = 64 clusters of 2
  k_head1<<<B_/4, 512>>>(Wa1, ba1, Wc1, bc1);
  k_head2<<<B_/4, 512>>>(Wa2, ba2, Wc2, bc2);
  k_head3<<<B_, 32>>>(Wa3, ba3, Wc3, bc3, log_std, out);
}